// round 3
// baseline (speedup 1.0000x reference)
#include <cuda_runtime.h>
#include <cstdint>

// Problem dims
#define B_ 8
#define L_ 1024
#define D_ 512
#define H_ 8
#define DK_ 64
#define BL_ (B_ * L_)               // 8192
#define ATT_OFF ((size_t)BL_ * D_)  // start of attn in d_out

// Projection GEMM tile config
#define BM 128
#define BN 64
#define BK 32
#define NTHR 256

// Fused attention config
#define QB 32      // queries per CTA
#define KC 128     // key chunk size
#define SP 1028    // S row stride (pad 4 -> conflict-free frag loads)
#define KP 68      // K/V tile row stride
#define ATTN_SMEM_FLOATS (QB * SP + KC * KP + QB * KP)
#define ATTN_SMEM_BYTES (ATTN_SMEM_FLOATS * 4)   // 175,104 B

// Scratch (static device globals — no allocation)
__device__ float g_Q[BL_ * D_];
__device__ float g_K[BL_ * D_];
__device__ float g_V[BL_ * D_];
__device__ float g_O[BL_ * D_];    // attn@V result; later reused for s2 output
__device__ float g_O2[BL_ * D_];   // fc output
__device__ float g_X[BL_ * D_];    // silu(film(h))
__device__ float g_lat[B_ * 2 * D_];

// ---------------------------------------------------------------------------
// tf32 helpers
// ---------------------------------------------------------------------------
__device__ __forceinline__ float tf32r(float x) {
    uint32_t o;
    asm("cvt.rna.tf32.f32 %0, %1;" : "=r"(o) : "f"(x));
    return __uint_as_float(o);
}

__device__ __forceinline__ void mma_tf32(float c[4], const float a[4], const float b[2]) {
    asm volatile(
        "mma.sync.aligned.m16n8k8.row.col.f32.tf32.tf32.f32 "
        "{%0,%1,%2,%3}, {%4,%5,%6,%7}, {%8,%9}, {%0,%1,%2,%3};"
        : "+f"(c[0]), "+f"(c[1]), "+f"(c[2]), "+f"(c[3])
        : "r"(__float_as_uint(a[0])), "r"(__float_as_uint(a[1])),
          "r"(__float_as_uint(a[2])), "r"(__float_as_uint(a[3])),
          "r"(__float_as_uint(b[0])), "r"(__float_as_uint(b[1])));
}

// ---------------------------------------------------------------------------
// Fused attention: scores + softmax + attn write + attn@V, one CTA per
// (b, h, 32-query block). grid (L/QB=32, B*H=64), 256 threads.
// ---------------------------------------------------------------------------
__global__ void __launch_bounds__(256) k_attn(float* __restrict__ attn) {
    extern __shared__ float sm[];
    float* Ss = sm;                     // [QB][SP]
    float* Ks = sm + QB * SP;           // [KC][KP], reused for V chunks + reduction
    float* Qs = Ks + KC * KP;           // [QB][KP]

    const int t = threadIdx.x;
    const int lane = t & 31, w = t >> 5;
    const int g = lane >> 2, tg = lane & 3;
    const int z = blockIdx.y;
    const int b = z >> 3, h = z & 7;
    const int q0 = blockIdx.x * QB;

    const float* Qg = g_Q + (size_t)b * L_ * D_ + h * DK_;
    const float* Kg = g_K + (size_t)b * L_ * D_ + h * DK_;
    const float* Vg = g_V + (size_t)b * L_ * D_ + h * DK_;
    float* attn_b = attn + (size_t)z * L_ * L_;

    // ---- load Q tile (QB x 64), tf32-rounded ----
    #pragma unroll
    for (int i = 0; i < 2; i++) {
        int idx = t + i * 256;          // 512 float4s total
        int r = idx >> 4, c4 = (idx & 15) << 2;
        float4 v = *(const float4*)(Qg + (size_t)(q0 + r) * D_ + c4);
        Qs[r * KP + c4 + 0] = tf32r(v.x);
        Qs[r * KP + c4 + 1] = tf32r(v.y);
        Qs[r * KP + c4 + 2] = tf32r(v.z);
        Qs[r * KP + c4 + 3] = tf32r(v.w);
    }

    // ---- phase 1: S = Q K^T / 8 into smem ----
    {
        const int wm = w & 1, wn = w >> 1;   // 2 (m16) x 4 (n32) warp grid
        for (int kc = 0; kc < L_ / KC; kc++) {
            __syncthreads();
            #pragma unroll
            for (int i = 0; i < 8; i++) {
                int idx = t + i * 256;
                int r = idx >> 4, c4 = (idx & 15) << 2;
                float4 v = *(const float4*)(Kg + (size_t)(kc * KC + r) * D_ + c4);
                Ks[r * KP + c4 + 0] = tf32r(v.x);
                Ks[r * KP + c4 + 1] = tf32r(v.y);
                Ks[r * KP + c4 + 2] = tf32r(v.z);
                Ks[r * KP + c4 + 3] = tf32r(v.w);
            }
            __syncthreads();

            float acc[4][4] = {};
            #pragma unroll
            for (int ks = 0; ks < DK_; ks += 8) {
                float a[4];
                int ar = wm * 16 + g;
                a[0] = Qs[ar * KP + ks + tg];
                a[1] = Qs[(ar + 8) * KP + ks + tg];
                a[2] = Qs[ar * KP + ks + tg + 4];
                a[3] = Qs[(ar + 8) * KP + ks + tg + 4];
                #pragma unroll
                for (int nt = 0; nt < 4; nt++) {
                    int n = wn * 32 + nt * 8 + g;
                    float bf[2];
                    bf[0] = Ks[n * KP + ks + tg];
                    bf[1] = Ks[n * KP + ks + tg + 4];
                    mma_tf32(acc[nt], a, bf);
                }
            }
            int row = wm * 16 + g;
            #pragma unroll
            for (int nt = 0; nt < 4; nt++) {
                int col = kc * KC + wn * 32 + nt * 8 + tg * 2;
                Ss[row * SP + col]           = acc[nt][0] * 0.125f;
                Ss[row * SP + col + 1]       = acc[nt][1] * 0.125f;
                Ss[(row + 8) * SP + col]     = acc[nt][2] * 0.125f;
                Ss[(row + 8) * SP + col + 1] = acc[nt][3] * 0.125f;
            }
        }
    }
    __syncthreads();

    // ---- phase 2: exact fp32 row softmax in smem; write attn to gmem ----
    #pragma unroll
    for (int rr = 0; rr < 4; rr++) {
        int r = w * 4 + rr;
        float4* row4 = (float4*)(Ss + r * SP);
        float m = -1e30f;
        #pragma unroll
        for (int i = 0; i < 8; i++) {
            float4 v = row4[lane + i * 32];
            m = fmaxf(m, fmaxf(fmaxf(v.x, v.y), fmaxf(v.z, v.w)));
        }
        #pragma unroll
        for (int s = 16; s; s >>= 1) m = fmaxf(m, __shfl_xor_sync(~0u, m, s));
        float sum = 0.f;
        #pragma unroll
        for (int i = 0; i < 8; i++) {
            float4 v = row4[lane + i * 32];
            v.x = __expf(v.x - m); v.y = __expf(v.y - m);
            v.z = __expf(v.z - m); v.w = __expf(v.w - m);
            row4[lane + i * 32] = v;
            sum += v.x + v.y + v.z + v.w;
        }
        #pragma unroll
        for (int s = 16; s; s >>= 1) sum += __shfl_xor_sync(~0u, sum, s);
        float inv = 1.0f / sum;
        float4* out4 = (float4*)(attn_b + (size_t)(q0 + r) * L_);
        #pragma unroll
        for (int i = 0; i < 8; i++) {
            float4 v = row4[lane + i * 32];
            v.x *= inv; v.y *= inv; v.z *= inv; v.w *= inv;
            row4[lane + i * 32] = v;
            out4[lane + i * 32] = v;
        }
    }

    // ---- phase 3: O = P V, warps split 2 (m16) x 4 (k-split) ----
    const int mh = w >> 2, kq = w & 3;
    float accO[8][4] = {};
    for (int kc = 0; kc < L_ / KC; kc++) {
        __syncthreads();
        #pragma unroll
        for (int i = 0; i < 8; i++) {
            int idx = t + i * 256;
            int r = idx >> 4, c4 = (idx & 15) << 2;
            float4 v = *(const float4*)(Vg + (size_t)(kc * KC + r) * D_ + c4);
            Ks[r * KP + c4 + 0] = tf32r(v.x);
            Ks[r * KP + c4 + 1] = tf32r(v.y);
            Ks[r * KP + c4 + 2] = tf32r(v.z);
            Ks[r * KP + c4 + 3] = tf32r(v.w);
        }
        __syncthreads();
        #pragma unroll
        for (int ks = 0; ks < 4; ks++) {
            int kb = kq * 32 + ks * 8;
            float a[4];
            int ar = mh * 16 + g;
            int col = kc * KC + kb + tg;
            a[0] = tf32r(Ss[ar * SP + col]);
            a[1] = tf32r(Ss[(ar + 8) * SP + col]);
            a[2] = tf32r(Ss[ar * SP + col + 4]);
            a[3] = tf32r(Ss[(ar + 8) * SP + col + 4]);
            #pragma unroll
            for (int nt = 0; nt < 8; nt++) {
                int n = nt * 8 + g;
                float bf[2];
                bf[0] = Ks[(kb + tg) * KP + n];
                bf[1] = Ks[(kb + tg + 4) * KP + n];
                mma_tf32(accO[nt], a, bf);
            }
        }
    }
    __syncthreads();
    // stage partials into Ks buffer as [warp][16][64]
    float* Rs = Ks;
    #pragma unroll
    for (int nt = 0; nt < 8; nt++) {
        int c = nt * 8 + tg * 2;
        Rs[(w * 16 + g) * 64 + c]         = accO[nt][0];
        Rs[(w * 16 + g) * 64 + c + 1]     = accO[nt][1];
        Rs[(w * 16 + g + 8) * 64 + c]     = accO[nt][2];
        Rs[(w * 16 + g + 8) * 64 + c + 1] = accO[nt][3];
    }
    __syncthreads();
    // reduce 4 k-split partials -> g_O
    {
        int m = t >> 3;           // 0..31 query row within tile
        int c = (t & 7) * 8;
        int mh2 = m >> 4, r16 = m & 15;
        float4 s0 = make_float4(0.f, 0.f, 0.f, 0.f), s1 = s0;
        #pragma unroll
        for (int kq2 = 0; kq2 < 4; kq2++) {
            const float* p = Rs + ((mh2 * 4 + kq2) * 16 + r16) * 64 + c;
            float4 v0 = *(const float4*)p;
            float4 v1 = *(const float4*)(p + 4);
            s0.x += v0.x; s0.y += v0.y; s0.z += v0.z; s0.w += v0.w;
            s1.x += v1.x; s1.y += v1.y; s1.z += v1.z; s1.w += v1.w;
        }
        float* Og = g_O + (size_t)(b * L_ + q0 + m) * D_ + h * DK_ + c;
        *(float4*)Og = s0;
        *(float4*)(Og + 4) = s1;
    }
}

// ---------------------------------------------------------------------------
// TF32 tensor-core GEMM tile body (projections / fc / s2).
// ---------------------------------------------------------------------------
__device__ __forceinline__ void gemm_tc_nn(
    const float* __restrict__ A, const float* __restrict__ Bg,
    const float* __restrict__ bias, float* __restrict__ C,
    int K, int lda, int ldb, int ldc)
{
    __shared__ float As[BM][BK + 4];
    __shared__ float Bs[BN][BK + 4];

    const int t = threadIdx.x;
    const int lane = t & 31, warp = t >> 5;
    const int wm = warp & 3, wn = warp >> 2;
    const int g = lane >> 2, tg = lane & 3;
    const int row0 = blockIdx.y * BM;
    const int col0 = blockIdx.x * BN;

    float acc[2][4][4] = {};

    for (int k0 = 0; k0 < K; k0 += BK) {
        #pragma unroll
        for (int i = 0; i < 4; i++) {
            int idx = t + i * NTHR;
            int r = idx >> 3, c4 = (idx & 7) << 2;
            float4 v = *(const float4*)(A + (size_t)(row0 + r) * lda + k0 + c4);
            As[r][c4 + 0] = tf32r(v.x);
            As[r][c4 + 1] = tf32r(v.y);
            As[r][c4 + 2] = tf32r(v.z);
            As[r][c4 + 3] = tf32r(v.w);
        }
        #pragma unroll
        for (int i = 0; i < 2; i++) {
            int idx = t + i * NTHR;
            int kk = idx >> 4, n4 = (idx & 15) << 2;
            float4 v = *(const float4*)(Bg + (size_t)(k0 + kk) * ldb + col0 + n4);
            Bs[n4 + 0][kk] = tf32r(v.x);
            Bs[n4 + 1][kk] = tf32r(v.y);
            Bs[n4 + 2][kk] = tf32r(v.z);
            Bs[n4 + 3][kk] = tf32r(v.w);
        }
        __syncthreads();

        #pragma unroll
        for (int ks = 0; ks < BK; ks += 8) {
            float a[2][4], bfr[4][2];
            #pragma unroll
            for (int mt = 0; mt < 2; mt++) {
                int r = wm * 32 + mt * 16 + g;
                a[mt][0] = As[r][ks + tg];
                a[mt][1] = As[r + 8][ks + tg];
                a[mt][2] = As[r][ks + tg + 4];
                a[mt][3] = As[r + 8][ks + tg + 4];
            }
            #pragma unroll
            for (int nt = 0; nt < 4; nt++) {
                int n = wn * 32 + nt * 8 + g;
                bfr[nt][0] = Bs[n][ks + tg];
                bfr[nt][1] = Bs[n][ks + tg + 4];
            }
            #pragma unroll
            for (int mt = 0; mt < 2; mt++)
                #pragma unroll
                for (int nt = 0; nt < 4; nt++)
                    mma_tf32(acc[mt][nt], a[mt], bfr[nt]);
        }
        __syncthreads();
    }

    #pragma unroll
    for (int mt = 0; mt < 2; mt++) {
        #pragma unroll
        for (int nt = 0; nt < 4; nt++) {
            int r = row0 + wm * 32 + mt * 16 + g;
            int c = col0 + wn * 32 + nt * 8 + tg * 2;
            float b0 = 0.f, b1 = 0.f;
            if (bias) { b0 = bias[c]; b1 = bias[c + 1]; }
            *(float2*)(C + (size_t)r * ldc + c) =
                make_float2(acc[mt][nt][0] + b0, acc[mt][nt][1] + b1);
            *(float2*)(C + (size_t)(r + 8) * ldc + c) =
                make_float2(acc[mt][nt][2] + b0, acc[mt][nt][3] + b1);
        }
    }
}

__global__ void __launch_bounds__(NTHR) k_proj_q(const float* __restrict__ A,
        const float* __restrict__ W, const float* __restrict__ bias) {
    gemm_tc_nn(A, W, bias, g_Q, D_, D_, D_, D_);
}
__global__ void __launch_bounds__(NTHR) k_proj_k(const float* __restrict__ A,
        const float* __restrict__ W, const float* __restrict__ bias) {
    gemm_tc_nn(A, W, bias, g_K, D_, D_, D_, D_);
}
__global__ void __launch_bounds__(NTHR) k_proj_v(const float* __restrict__ A,
        const float* __restrict__ W, const float* __restrict__ bias) {
    gemm_tc_nn(A, W, bias, g_V, D_, D_, D_, D_);
}
__global__ void __launch_bounds__(NTHR) k_fc(const float* __restrict__ W,
        const float* __restrict__ bias) {
    gemm_tc_nn(g_O, W, bias, g_O2, D_, D_, D_, D_);
}
__global__ void __launch_bounds__(NTHR) k_s2(const float* __restrict__ W,
        const float* __restrict__ bias) {
    gemm_tc_nn(g_X, W, bias, g_O, D_, D_, D_, D_);
}

// ---------------------------------------------------------------------------
// lat = silu(latent) @ Ws1 + bs1 -> g_lat [B, 2D]. grid (8,8), 128 thr
// ---------------------------------------------------------------------------
__global__ void k_lat(const float* __restrict__ latent, const float* __restrict__ Ws1,
                      const float* __restrict__ bs1) {
    int b = blockIdx.x;
    __shared__ float sl[D_];
    for (int i = threadIdx.x; i < D_; i += 128) {
        float x = latent[b * D_ + i];
        sl[i] = x / (1.0f + __expf(-x));
    }
    __syncthreads();
    int j = blockIdx.y * 128 + threadIdx.x;
    float acc = bs1[j];
    for (int k = 0; k < D_; k++) acc += sl[k] * Ws1[(size_t)k * (2 * D_) + j];
    g_lat[b * (2 * D_) + j] = acc;
}

// film: X = silu( LN(o2; en) * (1+scale) + shift ). one block (128 thr) per row
__global__ void k_film(const float* __restrict__ en_g, const float* __restrict__ en_b) {
    int row = blockIdx.x;
    int b = row >> 10;
    int t = threadIdx.x;
    float4 v = ((const float4*)(g_O2 + (size_t)row * D_))[t];
    __shared__ float red[128];

    red[t] = v.x + v.y + v.z + v.w;
    __syncthreads();
    for (int s = 64; s > 0; s >>= 1) {
        if (t < s) red[t] += red[t + s];
        __syncthreads();
    }
    float mean = red[0] * (1.0f / D_);
    __syncthreads();

    float dx = v.x - mean, dy = v.y - mean, dz = v.z - mean, dw = v.w - mean;
    red[t] = dx * dx + dy * dy + dz * dz + dw * dw;
    __syncthreads();
    for (int s = 64; s > 0; s >>= 1) {
        if (t < s) red[t] += red[t + s];
        __syncthreads();
    }
    float rstd = rsqrtf(red[0] * (1.0f / D_) + 1e-5f);

    int j = t * 4;
    float4 g4 = ((const float4*)en_g)[t];
    float4 b4 = ((const float4*)en_b)[t];
    float4 sc = *(const float4*)(g_lat + b * (2 * D_) + j);
    float4 sh = *(const float4*)(g_lat + b * (2 * D_) + D_ + j);

    float4 o;
    {
        float h;
        h = (dx * rstd * g4.x + b4.x) * (1.0f + sc.x) + sh.x; o.x = h / (1.0f + __expf(-h));
        h = (dy * rstd * g4.y + b4.y) * (1.0f + sc.y) + sh.y; o.y = h / (1.0f + __expf(-h));
        h = (dz * rstd * g4.z + b4.z) * (1.0f + sc.z) + sh.z; o.z = h / (1.0f + __expf(-h));
        h = (dw * rstd * g4.w + b4.w) * (1.0f + sc.w) + sh.w; o.w = h / (1.0f + __expf(-h));
    }
    ((float4*)(g_X + (size_t)row * D_))[t] = o;
}

// out = LN(h2 + residual; ln, eps=1e-6). one block (128 thr) per row
__global__ void k_final(const float* __restrict__ resid, const float* __restrict__ ln_g,
                        const float* __restrict__ ln_b, float* __restrict__ out) {
    int row = blockIdx.x;
    int t = threadIdx.x;
    float4 v = ((const float4*)(g_O + (size_t)row * D_))[t];
    float4 r = ((const float4*)(resid + (size_t)row * D_))[t];
    v.x += r.x; v.y += r.y; v.z += r.z; v.w += r.w;
    __shared__ float red[128];

    red[t] = v.x + v.y + v.z + v.w;
    __syncthreads();
    for (int s = 64; s > 0; s >>= 1) {
        if (t < s) red[t] += red[t + s];
        __syncthreads();
    }
    float mean = red[0] * (1.0f / D_);
    __syncthreads();

    float dx = v.x - mean, dy = v.y - mean, dz = v.z - mean, dw = v.w - mean;
    red[t] = dx * dx + dy * dy + dz * dz + dw * dw;
    __syncthreads();
    for (int s = 64; s > 0; s >>= 1) {
        if (t < s) red[t] += red[t + s];
        __syncthreads();
    }
    float rstd = rsqrtf(red[0] * (1.0f / D_) + 1e-6f);

    float4 g4 = ((const float4*)ln_g)[t];
    float4 b4 = ((const float4*)ln_b)[t];
    float4 o;
    o.x = dx * rstd * g4.x + b4.x;
    o.y = dy * rstd * g4.y + b4.y;
    o.z = dz * rstd * g4.z + b4.z;
    o.w = dw * rstd * g4.w + b4.w;
    ((float4*)(out + (size_t)row * D_))[t] = o;
}

// ---------------------------------------------------------------------------
extern "C" void kernel_launch(void* const* d_in, const int* in_sizes, int n_in,
                              void* d_out, int out_size) {
    const float* q      = (const float*)d_in[0];
    const float* k      = (const float*)d_in[1];
    const float* v      = (const float*)d_in[2];
    const float* latent = (const float*)d_in[3];
    const float* Wq  = (const float*)d_in[4];
    const float* bq  = (const float*)d_in[5];
    const float* Wk  = (const float*)d_in[6];
    const float* bk  = (const float*)d_in[7];
    const float* Wv  = (const float*)d_in[8];
    const float* bv  = (const float*)d_in[9];
    const float* Wfc = (const float*)d_in[10];
    const float* bfc = (const float*)d_in[11];
    const float* Ws1 = (const float*)d_in[12];
    const float* bs1 = (const float*)d_in[13];
    const float* Ws2 = (const float*)d_in[14];
    const float* bs2 = (const float*)d_in[15];
    const float* en_g = (const float*)d_in[16];
    const float* en_b = (const float*)d_in[17];
    const float* ln_g = (const float*)d_in[18];
    const float* ln_b = (const float*)d_in[19];

    float* out  = (float*)d_out;
    float* attn = out + ATT_OFF;

    cudaFuncSetAttribute(k_attn, cudaFuncAttributeMaxDynamicSharedMemorySize,
                         ATTN_SMEM_BYTES);

    dim3 t256(NTHR);
    dim3 gProj(D_ / BN, BL_ / BM);          // (8, 64)

    k_proj_q<<<gProj, t256>>>(q, Wq, bq);
    k_proj_k<<<gProj, t256>>>(k, Wk, bk);
    k_proj_v<<<gProj, t256>>>(v, Wv, bv);

    k_attn<<<dim3(L_ / QB, B_ * H_), 256, ATTN_SMEM_BYTES>>>(attn);

    k_fc<<<gProj, t256>>>(Wfc, bfc);
    k_lat<<<dim3(B_, 8), 128>>>(latent, Ws1, bs1);
    k_film<<<BL_, 128>>>(en_g, en_b);
    k_s2<<<gProj, t256>>>(Ws2, bs2);
    k_final<<<BL_, 128>>>(q, ln_g, ln_b, out);
}